// round 1
// baseline (speedup 1.0000x reference)
#include <cuda_runtime.h>
#include <math.h>

// Problem constants
#define B_    2
#define L_    1024
#define DM    512
#define E_    1024      // d_inner
#define NST   16        // d_state
#define RANK  32        // dt_rank
#define NTOK  (B_*L_)   // 2048
#define NLAYERS 6
#define EPS_RMS 1.1920929e-07f

// ---------------- scratch (static device memory; no allocations) ----------------
__device__ __align__(128) float g_h  [NTOK*DM];       // 4 MB residual stream
__device__ __align__(128) float g_xn [NTOK*DM];       // 4 MB rmsnorm out
__device__ __align__(128) float g_xz [NTOK*2*E_];     // 16 MB in_proj out (xi | z)
__device__ __align__(128) float g_xc [NTOK*E_];       // 8 MB conv+silu out
__device__ __align__(128) float g_dbc[NTOK*64];       // 0.5 MB x_proj out (dt_raw|B|C)
__device__ __align__(128) float g_dt [NTOK*E_];       // 8 MB dt after softplus
__device__ __align__(128) float g_y  [NTOK*E_];       // 8 MB scan+gate out

// ---------------- add position embedding + RMSNorm ----------------
// one block per token, 128 threads, 4 floats each (float4)
__global__ __launch_bounds__(128)
void addpos_rmsnorm(const float* __restrict__ h, const float* __restrict__ pos,
                    const float* __restrict__ w, float* __restrict__ out) {
    int tok = blockIdx.x;
    int i = threadIdx.x;                  // 0..127
    const float4* hp = (const float4*)(h   + (size_t)tok*DM);
    const float4* pp = (const float4*)(pos + (size_t)tok*DM);
    float4 hv = hp[i], pv = pp[i];
    hv.x += pv.x; hv.y += pv.y; hv.z += pv.z; hv.w += pv.w;
    float ss = hv.x*hv.x + hv.y*hv.y + hv.z*hv.z + hv.w*hv.w;
#pragma unroll
    for (int o = 16; o; o >>= 1) ss += __shfl_xor_sync(0xFFFFFFFFu, ss, o);
    __shared__ float sred[4];
    int lane = i & 31, wid = i >> 5;
    if (lane == 0) sred[wid] = ss;
    __syncthreads();
    ss = sred[0] + sred[1] + sred[2] + sred[3];
    float r = rsqrtf(ss * (1.0f/DM) + EPS_RMS);
    float4 wv = ((const float4*)w)[i];
    float4 o4 = make_float4(hv.x*r*wv.x, hv.y*r*wv.y, hv.z*r*wv.z, hv.w*r*wv.w);
    ((float4*)(out + (size_t)tok*DM))[i] = o4;
}

// ---------------- generic fp32 GEMM: C[M,N] = A[M,K] * B[N,K]^T ----------------
// 64x64 tile, BK=16, 256 threads, 4x4 per thread. Dims assumed multiples of tile
// (M=2048; N in {2048,1024,512,64}; K in {512,1024,32}) -> no bounds checks.
// EPI==1: softplus(x + bias[n]) epilogue (dt projection)
template<int EPI>
__global__ __launch_bounds__(256)
void gemm_atb(const float* __restrict__ A, int lda,
              const float* __restrict__ B, int ldb,
              float* __restrict__ C, int ldc, int K,
              const float* __restrict__ bias) {
    __shared__ float As[16][68];
    __shared__ float Bs[16][68];
    const int bm = blockIdx.y * 64;
    const int bn = blockIdx.x * 64;
    const int tid = threadIdx.x;
    const int tx = tid & 15, ty = tid >> 4;
    const int lr = tid >> 2;             // load row 0..63
    const int lc = (tid & 3) << 2;       // load col 0,4,8,12
    const float* Ap = A + (size_t)(bm + lr) * lda + lc;
    const float* Bp = B + (size_t)(bn + lr) * ldb + lc;
    float acc[4][4] = {};
    for (int k0 = 0; k0 < K; k0 += 16) {
        float4 av = *(const float4*)(Ap + k0);
        float4 bv = *(const float4*)(Bp + k0);
        As[lc+0][lr]=av.x; As[lc+1][lr]=av.y; As[lc+2][lr]=av.z; As[lc+3][lr]=av.w;
        Bs[lc+0][lr]=bv.x; Bs[lc+1][lr]=bv.y; Bs[lc+2][lr]=bv.z; Bs[lc+3][lr]=bv.w;
        __syncthreads();
#pragma unroll
        for (int kk = 0; kk < 16; kk++) {
            float4 a = *(const float4*)&As[kk][ty << 2];
            float4 b = *(const float4*)&Bs[kk][tx << 2];
            float ar[4] = {a.x, a.y, a.z, a.w};
            float br[4] = {b.x, b.y, b.z, b.w};
#pragma unroll
            for (int i = 0; i < 4; i++)
#pragma unroll
                for (int j = 0; j < 4; j++)
                    acc[i][j] += ar[i] * br[j];
        }
        __syncthreads();
    }
#pragma unroll
    for (int i = 0; i < 4; i++) {
        float r[4];
#pragma unroll
        for (int j = 0; j < 4; j++) {
            float v = acc[i][j];
            if (EPI == 1) {
                v += bias[bn + (tx << 2) + j];
                v = (v > 20.f) ? v : log1pf(__expf(v));
            }
            r[j] = v;
        }
        *(float4*)(C + (size_t)(bm + (ty << 2) + i) * ldc + bn + (tx << 2)) =
            make_float4(r[0], r[1], r[2], r[3]);
    }
}

// ---------------- depthwise causal conv1d (k=4) + bias + SiLU ----------------
// xi = first E_ columns of xz (row stride 2*E_)
__global__ __launch_bounds__(256)
void conv_silu(const float* __restrict__ xz, const float* __restrict__ w,
               const float* __restrict__ bias, float* __restrict__ xc) {
    int idx = blockIdx.x * blockDim.x + threadIdx.x;
    if (idx >= NTOK * E_) return;
    int e = idx & (E_ - 1);
    int t = (idx >> 10) & (L_ - 1);
    int b = idx >> 20;
    const float* xi = xz + (size_t)b * L_ * 2 * E_ + e;
    float4 wv = ((const float4*)w)[e];
    float s = bias[e];
    if (t >= 3) s += wv.x * xi[(t-3) * (2*E_)];
    if (t >= 2) s += wv.y * xi[(t-2) * (2*E_)];
    if (t >= 1) s += wv.z * xi[(t-1) * (2*E_)];
    s += wv.w * xi[t * (2*E_)];
    xc[idx] = s / (1.0f + __expf(-s));   // SiLU
}

// ---------------- selective scan + D skip + SiLU gate ----------------
// one warp per (b, e) channel; lanes 0..15 hold state n, lanes 16..31 idle-zero
__global__ __launch_bounds__(256)
void scan_kernel(const float* __restrict__ xc, const float* __restrict__ dbc,
                 const float* __restrict__ dt, const float* __restrict__ A_log,
                 const float* __restrict__ Dv, const float* __restrict__ xz,
                 float* __restrict__ y) {
    int gw   = (blockIdx.x * blockDim.x + threadIdx.x) >> 5;   // 0..2047
    int lane = threadIdx.x & 31;
    int b = gw >> 10;
    int e = gw & (E_ - 1);
    float a   = (lane < NST) ? -__expf(A_log[e * NST + lane]) : 0.0f;
    float d_e = Dv[e];
    const float* dtp  = dt  + (size_t)b * L_ * E_ + e;
    const float* up   = xc  + (size_t)b * L_ * E_ + e;
    const float* zp   = xz  + (size_t)b * L_ * 2 * E_ + E_ + e;
    const float* dbcp = dbc + (size_t)b * L_ * 64;
    float*       yp   = y   + (size_t)b * L_ * E_ + e;
    float h = 0.0f;
    for (int t = 0; t < L_; t++) {
        float dtv = dtp[(size_t)t * E_];
        float uv  = up[(size_t)t * E_];
        float bn  = (lane < NST) ? dbcp[t * 64 + 32 + lane] : 0.0f;
        float cn  = (lane < NST) ? dbcp[t * 64 + 48 + lane] : 0.0f;
        h = __expf(dtv * a) * h + (dtv * uv) * bn;
        float p = h * cn;
#pragma unroll
        for (int o = 16; o; o >>= 1) p += __shfl_xor_sync(0xFFFFFFFFu, p, o);
        if (lane == 0) {
            float zv = zp[(size_t)t * 2 * E_];
            yp[(size_t)t * E_] = (p + uv * d_e) * (zv / (1.0f + __expf(-zv)));
        }
    }
}

// ---------------- launch ----------------
extern "C" void kernel_launch(void* const* d_in, const int* in_sizes, int n_in,
                              void* d_out, int out_size) {
    (void)in_sizes; (void)n_in; (void)out_size;
    const float* x      = (const float*)d_in[0];
    const float* pos    = (const float*)d_in[1];
    const float* norm_w = (const float*)d_in[2];
    const float* in_w   = (const float*)d_in[3];
    const float* conv_w = (const float*)d_in[4];
    const float* conv_b = (const float*)d_in[5];
    const float* xproj  = (const float*)d_in[6];
    const float* dt_w   = (const float*)d_in[7];
    const float* dt_b   = (const float*)d_in[8];
    const float* A_log  = (const float*)d_in[9];
    const float* Dv     = (const float*)d_in[10];
    const float* out_w  = (const float*)d_in[11];
    float* out = (float*)d_out;

    float *h, *xn, *xz, *xc, *dbc, *dtb, *yb;
    cudaGetSymbolAddress((void**)&h,   g_h);
    cudaGetSymbolAddress((void**)&xn,  g_xn);
    cudaGetSymbolAddress((void**)&xz,  g_xz);
    cudaGetSymbolAddress((void**)&xc,  g_xc);
    cudaGetSymbolAddress((void**)&dbc, g_dbc);
    cudaGetSymbolAddress((void**)&dtb, g_dt);
    cudaGetSymbolAddress((void**)&yb,  g_y);

    for (int l = 0; l < NLAYERS; l++) {
        const float* hin  = (l == 0) ? x : h;
        float*       hout = (l == NLAYERS - 1) ? out : h;

        // 1) h + pos, rmsnorm -> xn
        addpos_rmsnorm<<<NTOK, 128>>>(hin, pos, norm_w, xn);

        // 2) xz = xn @ in_proj^T   (2048 x 2048, K=512)
        gemm_atb<0><<<dim3(2*E_/64, NTOK/64), 256>>>(
            xn, DM, in_w + (size_t)l * 2 * E_ * DM, DM, xz, 2*E_, DM, nullptr);

        // 3) conv + silu -> xc
        conv_silu<<<(NTOK*E_)/256, 256>>>(
            xz, conv_w + (size_t)l * E_ * 4, conv_b + (size_t)l * E_, xc);

        // 4) dbc = xc @ x_proj^T   (2048 x 64, K=1024)
        gemm_atb<0><<<dim3(64/64, NTOK/64), 256>>>(
            xc, E_, xproj + (size_t)l * 64 * E_, E_, dbc, 64, E_, nullptr);

        // 5) dt = softplus(dt_raw @ dt_w^T + dt_b)   (2048 x 1024, K=32, lda=64)
        gemm_atb<1><<<dim3(E_/64, NTOK/64), 256>>>(
            dbc, 64, dt_w + (size_t)l * E_ * RANK, RANK, dtb, E_, RANK,
            dt_b + (size_t)l * E_);

        // 6) selective scan + D skip + silu(z) gate -> y
        scan_kernel<<<(NTOK*32)/256, 256>>>(
            xc, dbc, dtb, A_log + (size_t)l * E_ * NST, Dv + (size_t)l * E_, xz, yb);

        // 7) hout = y @ out_w^T   (2048 x 512, K=1024)
        gemm_atb<0><<<dim3(DM/64, NTOK/64), 256>>>(
            yb, E_, out_w + (size_t)l * DM * E_, E_, hout, DM, E_, nullptr);
    }
}

// round 2
// speedup vs baseline: 1.1591x; 1.1591x over previous
#include <cuda_runtime.h>
#include <math.h>
#include <cstdint>

// Problem constants
#define B_    2
#define L_    1024
#define DM    512
#define E_    1024      // d_inner
#define NST   16        // d_state
#define RANK  32        // dt_rank
#define NTOK  (B_*L_)   // 2048
#define NLAYERS 6
#define EPS_RMS 1.1920929e-07f

// ---------------- scratch (static device memory; no allocations) ----------------
__device__ __align__(128) float g_h  [NTOK*DM];
__device__ __align__(128) float g_xn [NTOK*DM];
__device__ __align__(128) float g_xz [NTOK*2*E_];
__device__ __align__(128) float g_xc [NTOK*E_];
__device__ __align__(128) float g_dbc[NTOK*64];
__device__ __align__(128) float g_dt [NTOK*E_];
__device__ __align__(128) float g_y  [NTOK*E_];

// ---------------- add position embedding + RMSNorm ----------------
__global__ __launch_bounds__(128)
void addpos_rmsnorm(const float* __restrict__ h, const float* __restrict__ pos,
                    const float* __restrict__ w, float* __restrict__ out) {
    int tok = blockIdx.x;
    int i = threadIdx.x;
    const float4* hp = (const float4*)(h   + (size_t)tok*DM);
    const float4* pp = (const float4*)(pos + (size_t)tok*DM);
    float4 hv = hp[i], pv = pp[i];
    hv.x += pv.x; hv.y += pv.y; hv.z += pv.z; hv.w += pv.w;
    float ss = hv.x*hv.x + hv.y*hv.y + hv.z*hv.z + hv.w*hv.w;
#pragma unroll
    for (int o = 16; o; o >>= 1) ss += __shfl_xor_sync(0xFFFFFFFFu, ss, o);
    __shared__ float sred[4];
    int lane = i & 31, wid = i >> 5;
    if (lane == 0) sred[wid] = ss;
    __syncthreads();
    ss = sred[0] + sred[1] + sred[2] + sred[3];
    float r = rsqrtf(ss * (1.0f/DM) + EPS_RMS);
    float4 wv = ((const float4*)w)[i];
    float4 o4 = make_float4(hv.x*r*wv.x, hv.y*r*wv.y, hv.z*r*wv.z, hv.w*r*wv.w);
    ((float4*)(out + (size_t)tok*DM))[i] = o4;
}

// ---------------- tf32 tensor-core GEMM: C[M,N] = A[M,K] * B[N,K]^T ----------------
// CTA tile 128x64, BK=16, 256 threads (8 warps as 4x2), warp tile 32x32.
// Requirements (all satisfied here): M%128==0, N%64==0, K%16==0, lda/ldb/ldc %4==0.
// EPI==1: softplus(x + bias[n]) epilogue.

__device__ __forceinline__ uint32_t cvt_tf32(float x) {
    uint32_t r;
    asm("cvt.rna.tf32.f32 %0, %1;" : "=r"(r) : "f"(x));
    return r;
}

__device__ __forceinline__ void mma_tf32(float c[4], const uint32_t a[4], const uint32_t b[2]) {
    asm volatile(
        "mma.sync.aligned.m16n8k8.row.col.f32.tf32.tf32.f32 "
        "{%0,%1,%2,%3}, {%4,%5,%6,%7}, {%8,%9}, {%0,%1,%2,%3};"
        : "+f"(c[0]), "+f"(c[1]), "+f"(c[2]), "+f"(c[3])
        : "r"(a[0]), "r"(a[1]), "r"(a[2]), "r"(a[3]), "r"(b[0]), "r"(b[1]));
}

__device__ __forceinline__ void cp_async16(void* smem, const void* gmem) {
    uint32_t s = (uint32_t)__cvta_generic_to_shared(smem);
    asm volatile("cp.async.ca.shared.global [%0], [%1], 16;" :: "r"(s), "l"(gmem));
}

template<int EPI>
__global__ __launch_bounds__(256)
void gemm_mma(const float* __restrict__ A, int lda,
              const float* __restrict__ B, int ldb,
              float* __restrict__ C, int ldc, int K,
              const float* __restrict__ bias) {
    constexpr int BM = 128, BN = 64, BK = 16, PAD = 4;
    __shared__ float As[2][BM][BK+PAD];   // 2*128*20*4 = 20480 B
    __shared__ float Bs[2][BN][BK+PAD];   // 2*64*20*4  = 10240 B

    const int bm = blockIdx.y * BM;
    const int bn = blockIdx.x * BN;
    const int tid  = threadIdx.x;
    const int warp = tid >> 5, lane = tid & 31;
    const int wm = (warp >> 1) * 32;      // warp m-offset (4 warps)
    const int wn = (warp & 1) * 32;       // warp n-offset (2 warps)

    // global -> smem mapping: A 128x16 = 512 f4 (2/thread), B 64x16 = 256 f4 (1/thread)
    const int arow = tid >> 1, ac = (tid & 1) * 8;
    const int brow = tid >> 2, bc = (tid & 3) * 4;
    const float* Ag = A + (size_t)(bm + arow) * lda + ac;
    const float* Bg = B + (size_t)(bn + brow) * ldb + bc;

    float acc[2][4][4] = {};              // [m16][n8][frag]

    const int nk = K / BK;

    // prefetch tile 0
    cp_async16(&As[0][arow][ac],     Ag);
    cp_async16(&As[0][arow][ac + 4], Ag + 4);
    cp_async16(&Bs[0][brow][bc],     Bg);
    asm volatile("cp.async.commit_group;");

    for (int it = 0; it < nk; ++it) {
        if (it + 1 < nk) {
            int nb = (it + 1) & 1;
            const float* a = Ag + (it + 1) * BK;
            const float* b = Bg + (it + 1) * BK;
            cp_async16(&As[nb][arow][ac],     a);
            cp_async16(&As[nb][arow][ac + 4], a + 4);
            cp_async16(&Bs[nb][brow][bc],     b);
        }
        asm volatile("cp.async.commit_group;");
        asm volatile("cp.async.wait_group 1;");
        __syncthreads();

        const int buf = it & 1;
        const int r0 = wm + (lane >> 2);
        const int nr = wn + (lane >> 2);
#pragma unroll
        for (int ks = 0; ks < BK; ks += 8) {
            const int c0 = ks + (lane & 3);
            uint32_t afrag[2][4], bfrag[4][2];
#pragma unroll
            for (int mi = 0; mi < 2; mi++) {
                afrag[mi][0] = cvt_tf32(As[buf][r0 + mi*16    ][c0    ]);
                afrag[mi][1] = cvt_tf32(As[buf][r0 + mi*16 + 8][c0    ]);
                afrag[mi][2] = cvt_tf32(As[buf][r0 + mi*16    ][c0 + 4]);
                afrag[mi][3] = cvt_tf32(As[buf][r0 + mi*16 + 8][c0 + 4]);
            }
#pragma unroll
            for (int ni = 0; ni < 4; ni++) {
                bfrag[ni][0] = cvt_tf32(Bs[buf][nr + ni*8][c0    ]);
                bfrag[ni][1] = cvt_tf32(Bs[buf][nr + ni*8][c0 + 4]);
            }
#pragma unroll
            for (int mi = 0; mi < 2; mi++)
#pragma unroll
                for (int ni = 0; ni < 4; ni++)
                    mma_tf32(acc[mi][ni], afrag[mi], bfrag[ni]);
        }
        __syncthreads();
    }

    // epilogue
#pragma unroll
    for (int mi = 0; mi < 2; mi++) {
        const int row0 = bm + wm + mi*16 + (lane >> 2);
#pragma unroll
        for (int ni = 0; ni < 4; ni++) {
            const int col = bn + wn + ni*8 + 2*(lane & 3);
            float v0 = acc[mi][ni][0], v1 = acc[mi][ni][1];
            float v2 = acc[mi][ni][2], v3 = acc[mi][ni][3];
            if (EPI == 1) {
                float b0v = bias[col], b1v = bias[col + 1];
                v0 += b0v; v1 += b1v; v2 += b0v; v3 += b1v;
                v0 = (v0 > 20.f) ? v0 : log1pf(__expf(v0));
                v1 = (v1 > 20.f) ? v1 : log1pf(__expf(v1));
                v2 = (v2 > 20.f) ? v2 : log1pf(__expf(v2));
                v3 = (v3 > 20.f) ? v3 : log1pf(__expf(v3));
            }
            *(float2*)(C + (size_t)row0       * ldc + col) = make_float2(v0, v1);
            *(float2*)(C + (size_t)(row0 + 8) * ldc + col) = make_float2(v2, v3);
        }
    }
}

// ---------------- depthwise causal conv1d (k=4) + bias + SiLU ----------------
__global__ __launch_bounds__(256)
void conv_silu(const float* __restrict__ xz, const float* __restrict__ w,
               const float* __restrict__ bias, float* __restrict__ xc) {
    int idx = blockIdx.x * blockDim.x + threadIdx.x;
    if (idx >= NTOK * E_) return;
    int e = idx & (E_ - 1);
    int t = (idx >> 10) & (L_ - 1);
    int b = idx >> 20;
    const float* xi = xz + (size_t)b * L_ * 2 * E_ + e;
    float4 wv = ((const float4*)w)[e];
    float s = bias[e];
    if (t >= 3) s += wv.x * xi[(t-3) * (2*E_)];
    if (t >= 2) s += wv.y * xi[(t-2) * (2*E_)];
    if (t >= 1) s += wv.z * xi[(t-1) * (2*E_)];
    s += wv.w * xi[t * (2*E_)];
    xc[idx] = s / (1.0f + __expf(-s));
}

// ---------------- selective scan + D skip + SiLU gate ----------------
__global__ __launch_bounds__(256)
void scan_kernel(const float* __restrict__ xc, const float* __restrict__ dbc,
                 const float* __restrict__ dt, const float* __restrict__ A_log,
                 const float* __restrict__ Dv, const float* __restrict__ xz,
                 float* __restrict__ y) {
    int gw   = (blockIdx.x * blockDim.x + threadIdx.x) >> 5;
    int lane = threadIdx.x & 31;
    int b = gw >> 10;
    int e = gw & (E_ - 1);
    float a   = (lane < NST) ? -__expf(A_log[e * NST + lane]) : 0.0f;
    float d_e = Dv[e];
    const float* dtp  = dt  + (size_t)b * L_ * E_ + e;
    const float* up   = xc  + (size_t)b * L_ * E_ + e;
    const float* zp   = xz  + (size_t)b * L_ * 2 * E_ + E_ + e;
    const float* dbcp = dbc + (size_t)b * L_ * 64;
    float*       yp   = y   + (size_t)b * L_ * E_ + e;
    float h = 0.0f;
    for (int t = 0; t < L_; t++) {
        float dtv = dtp[(size_t)t * E_];
        float uv  = up[(size_t)t * E_];
        float bn  = (lane < NST) ? dbcp[t * 64 + 32 + lane] : 0.0f;
        float cn  = (lane < NST) ? dbcp[t * 64 + 48 + lane] : 0.0f;
        h = __expf(dtv * a) * h + (dtv * uv) * bn;
        float p = h * cn;
#pragma unroll
        for (int o = 16; o; o >>= 1) p += __shfl_xor_sync(0xFFFFFFFFu, p, o);
        if (lane == 0) {
            float zv = zp[(size_t)t * 2 * E_];
            yp[(size_t)t * E_] = (p + uv * d_e) * (zv / (1.0f + __expf(-zv)));
        }
    }
}

// ---------------- launch ----------------
extern "C" void kernel_launch(void* const* d_in, const int* in_sizes, int n_in,
                              void* d_out, int out_size) {
    (void)in_sizes; (void)n_in; (void)out_size;
    const float* x      = (const float*)d_in[0];
    const float* pos    = (const float*)d_in[1];
    const float* norm_w = (const float*)d_in[2];
    const float* in_w   = (const float*)d_in[3];
    const float* conv_w = (const float*)d_in[4];
    const float* conv_b = (const float*)d_in[5];
    const float* xproj  = (const float*)d_in[6];
    const float* dt_w   = (const float*)d_in[7];
    const float* dt_b   = (const float*)d_in[8];
    const float* A_log  = (const float*)d_in[9];
    const float* Dv     = (const float*)d_in[10];
    const float* out_w  = (const float*)d_in[11];
    float* out = (float*)d_out;

    float *h, *xn, *xz, *xc, *dbc, *dtb, *yb;
    cudaGetSymbolAddress((void**)&h,   g_h);
    cudaGetSymbolAddress((void**)&xn,  g_xn);
    cudaGetSymbolAddress((void**)&xz,  g_xz);
    cudaGetSymbolAddress((void**)&xc,  g_xc);
    cudaGetSymbolAddress((void**)&dbc, g_dbc);
    cudaGetSymbolAddress((void**)&dtb, g_dt);
    cudaGetSymbolAddress((void**)&yb,  g_y);

    for (int l = 0; l < NLAYERS; l++) {
        const float* hin  = (l == 0) ? x : h;
        float*       hout = (l == NLAYERS - 1) ? out : h;

        // 1) h + pos, rmsnorm -> xn
        addpos_rmsnorm<<<NTOK, 128>>>(hin, pos, norm_w, xn);

        // 2) xz = xn @ in_proj^T   (2048 x 2048, K=512)
        gemm_mma<0><<<dim3(2*E_/64, NTOK/128), 256>>>(
            xn, DM, in_w + (size_t)l * 2 * E_ * DM, DM, xz, 2*E_, DM, nullptr);

        // 3) conv + silu -> xc
        conv_silu<<<(NTOK*E_)/256, 256>>>(
            xz, conv_w + (size_t)l * E_ * 4, conv_b + (size_t)l * E_, xc);

        // 4) dbc = xc @ x_proj^T   (2048 x 64, K=1024)
        gemm_mma<0><<<dim3(1, NTOK/128), 256>>>(
            xc, E_, xproj + (size_t)l * 64 * E_, E_, dbc, 64, E_, nullptr);

        // 5) dt = softplus(dt_raw @ dt_w^T + dt_b)   (2048 x 1024, K=32)
        gemm_mma<1><<<dim3(E_/64, NTOK/128), 256>>>(
            dbc, 64, dt_w + (size_t)l * E_ * RANK, RANK, dtb, E_, RANK,
            dt_b + (size_t)l * E_);

        // 6) selective scan + D skip + silu(z) gate -> y
        scan_kernel<<<(NTOK*32)/256, 256>>>(
            xc, dbc, dtb, A_log + (size_t)l * E_ * NST, Dv + (size_t)l * E_, xz, yb);

        // 7) hout = y @ out_w^T   (2048 x 512, K=1024)
        gemm_mma<0><<<dim3(DM/64, NTOK/128), 256>>>(
            yb, E_, out_w + (size_t)l * DM * E_, E_, hout, DM, E_, nullptr);
    }
}

// round 3
// speedup vs baseline: 2.6958x; 2.3259x over previous
#include <cuda_runtime.h>
#include <math.h>
#include <cstdint>

// Problem constants
#define B_    2
#define L_    1024
#define DM    512
#define E_    1024      // d_inner
#define NST   16        // d_state
#define RANK  32        // dt_rank
#define NTOK  (B_*L_)   // 2048
#define NLAYERS 6
#define EPS_RMS 1.1920929e-07f
#define XPROJ_SPLIT 8

// ---------------- scratch (static device memory; no allocations) ----------------
__device__ __align__(128) float g_h  [NTOK*DM];
__device__ __align__(128) float g_xn [NTOK*DM];
__device__ __align__(128) float g_xz [NTOK*2*E_];
__device__ __align__(128) float g_xc [NTOK*E_];
__device__ __align__(128) float g_dbc[NTOK*64];
__device__ __align__(128) float g_dbc_part[XPROJ_SPLIT*NTOK*64];
__device__ __align__(128) float g_dt [NTOK*E_];
__device__ __align__(128) float g_y  [NTOK*E_];

// ---------------- add position embedding + RMSNorm ----------------
__global__ __launch_bounds__(128)
void addpos_rmsnorm(const float* __restrict__ h, const float* __restrict__ pos,
                    const float* __restrict__ w, float* __restrict__ out) {
    int tok = blockIdx.x;
    int i = threadIdx.x;
    const float4* hp = (const float4*)(h   + (size_t)tok*DM);
    const float4* pp = (const float4*)(pos + (size_t)tok*DM);
    float4 hv = hp[i], pv = pp[i];
    hv.x += pv.x; hv.y += pv.y; hv.z += pv.z; hv.w += pv.w;
    float ss = hv.x*hv.x + hv.y*hv.y + hv.z*hv.z + hv.w*hv.w;
#pragma unroll
    for (int o = 16; o; o >>= 1) ss += __shfl_xor_sync(0xFFFFFFFFu, ss, o);
    __shared__ float sred[4];
    int lane = i & 31, wid = i >> 5;
    if (lane == 0) sred[wid] = ss;
    __syncthreads();
    ss = sred[0] + sred[1] + sred[2] + sred[3];
    float r = rsqrtf(ss * (1.0f/DM) + EPS_RMS);
    float4 wv = ((const float4*)w)[i];
    float4 o4 = make_float4(hv.x*r*wv.x, hv.y*r*wv.y, hv.z*r*wv.z, hv.w*r*wv.w);
    ((float4*)(out + (size_t)tok*DM))[i] = o4;
}

// ---------------- tf32 tensor-core GEMM: C[M,N] = A[M,K] * B[N,K]^T ----------------
// CTA tile 128x64, BK=16, 256 threads (8 warps, 4x2), warp tile 32x32.
// gridDim.z = split-K factor; each z-slice handles K/gridDim.z and writes to
// C + blockIdx.z * zstride (deterministic split-K via scratch + reduce kernel).
// EPI==1: softplus(x + bias[n]) epilogue.

__device__ __forceinline__ uint32_t cvt_tf32(float x) {
    uint32_t r;
    asm("cvt.rna.tf32.f32 %0, %1;" : "=r"(r) : "f"(x));
    return r;
}

__device__ __forceinline__ void mma_tf32(float c[4], const uint32_t a[4], const uint32_t b[2]) {
    asm volatile(
        "mma.sync.aligned.m16n8k8.row.col.f32.tf32.tf32.f32 "
        "{%0,%1,%2,%3}, {%4,%5,%6,%7}, {%8,%9}, {%0,%1,%2,%3};"
        : "+f"(c[0]), "+f"(c[1]), "+f"(c[2]), "+f"(c[3])
        : "r"(a[0]), "r"(a[1]), "r"(a[2]), "r"(a[3]), "r"(b[0]), "r"(b[1]));
}

__device__ __forceinline__ void cp_async16(void* smem, const void* gmem) {
    uint32_t s = (uint32_t)__cvta_generic_to_shared(smem);
    asm volatile("cp.async.ca.shared.global [%0], [%1], 16;" :: "r"(s), "l"(gmem));
}

template<int EPI>
__global__ __launch_bounds__(256)
void gemm_mma(const float* __restrict__ A, int lda,
              const float* __restrict__ B, int ldb,
              float* __restrict__ C, int ldc, int K,
              const float* __restrict__ bias, size_t zstride) {
    constexpr int BM = 128, BN = 64, BK = 16, PAD = 4;
    __shared__ float As[2][BM][BK+PAD];
    __shared__ float Bs[2][BN][BK+PAD];

    const int bm = blockIdx.y * BM;
    const int bn = blockIdx.x * BN;
    const int Kc = K / gridDim.z;
    const int kc0 = blockIdx.z * Kc;
    const int tid  = threadIdx.x;
    const int warp = tid >> 5, lane = tid & 31;
    const int wm = (warp >> 1) * 32;
    const int wn = (warp & 1) * 32;

    const int arow = tid >> 1, ac = (tid & 1) * 8;
    const int brow = tid >> 2, bc = (tid & 3) * 4;
    const float* Ag = A + (size_t)(bm + arow) * lda + kc0 + ac;
    const float* Bg = B + (size_t)(bn + brow) * ldb + kc0 + bc;

    float acc[2][4][4] = {};
    const int nk = Kc / BK;

    cp_async16(&As[0][arow][ac],     Ag);
    cp_async16(&As[0][arow][ac + 4], Ag + 4);
    cp_async16(&Bs[0][brow][bc],     Bg);
    asm volatile("cp.async.commit_group;");

    for (int it = 0; it < nk; ++it) {
        if (it + 1 < nk) {
            int nb = (it + 1) & 1;
            const float* a = Ag + (it + 1) * BK;
            const float* b = Bg + (it + 1) * BK;
            cp_async16(&As[nb][arow][ac],     a);
            cp_async16(&As[nb][arow][ac + 4], a + 4);
            cp_async16(&Bs[nb][brow][bc],     b);
        }
        asm volatile("cp.async.commit_group;");
        asm volatile("cp.async.wait_group 1;");
        __syncthreads();

        const int buf = it & 1;
        const int r0 = wm + (lane >> 2);
        const int nr = wn + (lane >> 2);
#pragma unroll
        for (int ks = 0; ks < BK; ks += 8) {
            const int c0 = ks + (lane & 3);
            uint32_t afrag[2][4], bfrag[4][2];
#pragma unroll
            for (int mi = 0; mi < 2; mi++) {
                afrag[mi][0] = cvt_tf32(As[buf][r0 + mi*16    ][c0    ]);
                afrag[mi][1] = cvt_tf32(As[buf][r0 + mi*16 + 8][c0    ]);
                afrag[mi][2] = cvt_tf32(As[buf][r0 + mi*16    ][c0 + 4]);
                afrag[mi][3] = cvt_tf32(As[buf][r0 + mi*16 + 8][c0 + 4]);
            }
#pragma unroll
            for (int ni = 0; ni < 4; ni++) {
                bfrag[ni][0] = cvt_tf32(Bs[buf][nr + ni*8][c0    ]);
                bfrag[ni][1] = cvt_tf32(Bs[buf][nr + ni*8][c0 + 4]);
            }
#pragma unroll
            for (int mi = 0; mi < 2; mi++)
#pragma unroll
                for (int ni = 0; ni < 4; ni++)
                    mma_tf32(acc[mi][ni], afrag[mi], bfrag[ni]);
        }
        __syncthreads();
    }

    float* Cw = C + (size_t)blockIdx.z * zstride;
#pragma unroll
    for (int mi = 0; mi < 2; mi++) {
        const int row0 = bm + wm + mi*16 + (lane >> 2);
#pragma unroll
        for (int ni = 0; ni < 4; ni++) {
            const int col = bn + wn + ni*8 + 2*(lane & 3);
            float v0 = acc[mi][ni][0], v1 = acc[mi][ni][1];
            float v2 = acc[mi][ni][2], v3 = acc[mi][ni][3];
            if (EPI == 1) {
                float b0v = bias[col], b1v = bias[col + 1];
                v0 += b0v; v1 += b1v; v2 += b0v; v3 += b1v;
                v0 = (v0 > 20.f) ? v0 : log1pf(__expf(v0));
                v1 = (v1 > 20.f) ? v1 : log1pf(__expf(v1));
                v2 = (v2 > 20.f) ? v2 : log1pf(__expf(v2));
                v3 = (v3 > 20.f) ? v3 : log1pf(__expf(v3));
            }
            *(float2*)(Cw + (size_t)row0       * ldc + col) = make_float2(v0, v1);
            *(float2*)(Cw + (size_t)(row0 + 8) * ldc + col) = make_float2(v2, v3);
        }
    }
}

// ---------------- split-K partial reduce (deterministic) ----------------
__global__ __launch_bounds__(256)
void reduce_parts(const float* __restrict__ part, float* __restrict__ out, int n) {
    int i = blockIdx.x * blockDim.x + threadIdx.x;
    if (i >= n) return;
    float s = 0.f;
#pragma unroll
    for (int j = 0; j < XPROJ_SPLIT; j++) s += part[(size_t)j * n + i];
    out[i] = s;
}

// ---------------- depthwise causal conv1d (k=4) + bias + SiLU ----------------
__global__ __launch_bounds__(256)
void conv_silu(const float* __restrict__ xz, const float* __restrict__ w,
               const float* __restrict__ bias, float* __restrict__ xc) {
    int idx = blockIdx.x * blockDim.x + threadIdx.x;
    if (idx >= NTOK * E_) return;
    int e = idx & (E_ - 1);
    int t = (idx >> 10) & (L_ - 1);
    int b = idx >> 20;
    const float* xi = xz + (size_t)b * L_ * 2 * E_ + e;
    float4 wv = ((const float4*)w)[e];
    float s = bias[e];
    if (t >= 3) s += wv.x * xi[(t-3) * (2*E_)];
    if (t >= 2) s += wv.y * xi[(t-2) * (2*E_)];
    if (t >= 1) s += wv.z * xi[(t-1) * (2*E_)];
    s += wv.w * xi[t * (2*E_)];
    xc[idx] = s / (1.0f + __expf(-s));
}

// ---------------- selective scan + D skip + SiLU gate (8x unrolled) ----------------
// one warp per (b,e) channel; lanes 0..15 hold state n. Per 8-step block:
// batched loads (MLP~40), exp off the h critical path, 8 interleaved reductions.
__global__ __launch_bounds__(256)
void scan_kernel(const float* __restrict__ xc, const float* __restrict__ dbc,
                 const float* __restrict__ dt, const float* __restrict__ A_log,
                 const float* __restrict__ Dv, const float* __restrict__ xz,
                 float* __restrict__ y) {
    int gw   = (blockIdx.x * blockDim.x + threadIdx.x) >> 5;
    int lane = threadIdx.x & 31;
    int b = gw >> 10;
    int e = gw & (E_ - 1);
    float a   = (lane < NST) ? -__expf(A_log[e * NST + lane]) : 0.0f;
    float d_e = Dv[e];
    const float* dtp  = dt  + (size_t)b * L_ * E_ + e;
    const float* up   = xc  + (size_t)b * L_ * E_ + e;
    const float* zp   = xz  + (size_t)b * L_ * 2 * E_ + E_ + e;
    const float* dbcp = dbc + (size_t)b * L_ * 64;
    float*       yp   = y   + (size_t)b * L_ * E_ + e;
    float h = 0.0f;
    for (int t0 = 0; t0 < L_; t0 += 8) {
        float dtv[8], uv[8], bn[8], cn[8], zv[8];
#pragma unroll
        for (int j = 0; j < 8; j++) {
            int t = t0 + j;
            dtv[j] = dtp[(size_t)t * E_];
            uv[j]  = up[(size_t)t * E_];
            zv[j]  = zp[(size_t)t * 2 * E_];
            bn[j]  = (lane < NST) ? dbcp[t * 64 + 32 + lane] : 0.0f;
            cn[j]  = (lane < NST) ? dbcp[t * 64 + 48 + lane] : 0.0f;
        }
        float p[8];
#pragma unroll
        for (int j = 0; j < 8; j++) {
            float ev = __expf(dtv[j] * a);
            h = ev * h + (dtv[j] * uv[j]) * bn[j];
            p[j] = h * cn[j];
        }
#pragma unroll
        for (int o = 8; o; o >>= 1)
#pragma unroll
            for (int j = 0; j < 8; j++)
                p[j] += __shfl_xor_sync(0xFFFFFFFFu, p[j], o);
        if (lane == 0) {
#pragma unroll
            for (int j = 0; j < 8; j++) {
                float sz = zv[j] / (1.0f + __expf(-zv[j]));
                yp[(size_t)(t0 + j) * E_] = (p[j] + uv[j] * d_e) * sz;
            }
        }
    }
}

// ---------------- launch ----------------
extern "C" void kernel_launch(void* const* d_in, const int* in_sizes, int n_in,
                              void* d_out, int out_size) {
    (void)in_sizes; (void)n_in; (void)out_size;
    const float* x      = (const float*)d_in[0];
    const float* pos    = (const float*)d_in[1];
    const float* norm_w = (const float*)d_in[2];
    const float* in_w   = (const float*)d_in[3];
    const float* conv_w = (const float*)d_in[4];
    const float* conv_b = (const float*)d_in[5];
    const float* xproj  = (const float*)d_in[6];
    const float* dt_w   = (const float*)d_in[7];
    const float* dt_b   = (const float*)d_in[8];
    const float* A_log  = (const float*)d_in[9];
    const float* Dv     = (const float*)d_in[10];
    const float* out_w  = (const float*)d_in[11];
    float* out = (float*)d_out;

    float *h, *xn, *xz, *xc, *dbc, *dbcp, *dtb, *yb;
    cudaGetSymbolAddress((void**)&h,    g_h);
    cudaGetSymbolAddress((void**)&xn,   g_xn);
    cudaGetSymbolAddress((void**)&xz,   g_xz);
    cudaGetSymbolAddress((void**)&xc,   g_xc);
    cudaGetSymbolAddress((void**)&dbc,  g_dbc);
    cudaGetSymbolAddress((void**)&dbcp, g_dbc_part);
    cudaGetSymbolAddress((void**)&dtb,  g_dt);
    cudaGetSymbolAddress((void**)&yb,   g_y);

    for (int l = 0; l < NLAYERS; l++) {
        const float* hin  = (l == 0) ? x : h;
        float*       hout = (l == NLAYERS - 1) ? out : h;

        // 1) h + pos, rmsnorm -> xn
        addpos_rmsnorm<<<NTOK, 128>>>(hin, pos, norm_w, xn);

        // 2) xz = xn @ in_proj^T   (2048 x 2048, K=512)
        gemm_mma<0><<<dim3(2*E_/64, NTOK/128, 1), 256>>>(
            xn, DM, in_w + (size_t)l * 2 * E_ * DM, DM, xz, 2*E_, DM, nullptr, 0);

        // 3) conv + silu -> xc
        conv_silu<<<(NTOK*E_)/256, 256>>>(
            xz, conv_w + (size_t)l * E_ * 4, conv_b + (size_t)l * E_, xc);

        // 4) dbc = xc @ x_proj^T   (2048 x 64, K=1024) split-K x8 + reduce
        gemm_mma<0><<<dim3(1, NTOK/128, XPROJ_SPLIT), 256>>>(
            xc, E_, xproj + (size_t)l * 64 * E_, E_, dbcp, 64, E_, nullptr,
            (size_t)NTOK * 64);
        reduce_parts<<<(NTOK*64)/256, 256>>>(dbcp, dbc, NTOK*64);

        // 5) dt = softplus(dt_raw @ dt_w^T + dt_b)   (2048 x 1024, K=32)
        gemm_mma<1><<<dim3(E_/64, NTOK/128, 1), 256>>>(
            dbc, 64, dt_w + (size_t)l * E_ * RANK, RANK, dtb, E_, RANK,
            dt_b + (size_t)l * E_, 0);

        // 6) selective scan + D skip + silu(z) gate -> y
        scan_kernel<<<(NTOK*32)/256, 256>>>(
            xc, dbc, dtb, A_log + (size_t)l * E_ * NST, Dv + (size_t)l * E_, xz, yb);

        // 7) hout = y @ out_w^T   (2048 x 512, K=1024)
        gemm_mma<0><<<dim3(DM/64, NTOK/128, 1), 256>>>(
            yb, E_, out_w + (size_t)l * DM * E_, E_, hout, DM, E_, nullptr, 0);
    }
}